// round 13
// baseline (speedup 1.0000x reference)
#include <cuda_runtime.h>
#include <cuda_fp16.h>
#include <cstdint>

// Fixed shapes
#define BATCH 2
#define HEADS 16
#define SEQ   2048
#define DK    64
#define BH    (BATCH*HEADS)

#define TQ 64            // query rows per CTA
#define TK 64            // keys per tile (compacted)

// smem byte offsets (static buffer)
#define QB    0          // Q 64x64 half  (9216)
#define KB    9216       // K tile (9216)
#define VB    18432      // V tile / pass1 K buf1 (9216)
#define ADDB  27648      // addend float[2048] (8192)
#define CMB   35840      // column map int[2048] (8192)
#define LB    44032      // L float[2][64] (512)
#define ILB   44544      // invL float[64] (256)
#define SMEM_BYTES 44800

#define E16F   8886110.5f      // e^16
#define INVE16 1.1253517e-7f   // e^-16

// compacted fp16 K/V + per-batch column map (static device scratch)
__device__ __half g_Kc[(size_t)BH * SEQ * DK];
__device__ __half g_Vc[(size_t)BH * SEQ * DK];
__device__ int    g_cmap[BATCH * SEQ];
__device__ int    g_nmask[BATCH];

__device__ __forceinline__ uint32_t pack2(float lo, float hi) {
    __half2 h = __floats2half2_rn(lo, hi);
    return *reinterpret_cast<uint32_t*>(&h);
}
__device__ __forceinline__ uint2 f4h(float4 v) {
    return make_uint2(pack2(v.x, v.y), pack2(v.z, v.w));
}
__device__ __forceinline__ void mma16(float c[4],
                                      uint32_t a0, uint32_t a1, uint32_t a2, uint32_t a3,
                                      uint32_t b0, uint32_t b1) {
    asm volatile(
        "mma.sync.aligned.m16n8k16.row.col.f32.f16.f16.f32 "
        "{%0,%1,%2,%3}, {%4,%5,%6,%7}, {%8,%9}, {%0,%1,%2,%3};\n"
        : "+f"(c[0]), "+f"(c[1]), "+f"(c[2]), "+f"(c[3])
        : "r"(a0), "r"(a1), "r"(a2), "r"(a3), "r"(b0), "r"(b1));
}
__device__ __forceinline__ void ldsm4(uint32_t& r0, uint32_t& r1, uint32_t& r2, uint32_t& r3,
                                      uint32_t a) {
    asm volatile("ldmatrix.sync.aligned.m8n8.x4.shared.b16 {%0,%1,%2,%3}, [%4];"
                 : "=r"(r0), "=r"(r1), "=r"(r2), "=r"(r3) : "r"(a));
}
__device__ __forceinline__ void ldsm4t(uint32_t& r0, uint32_t& r1, uint32_t& r2, uint32_t& r3,
                                       uint32_t a) {
    asm volatile("ldmatrix.sync.aligned.m8n8.x4.trans.shared.b16 {%0,%1,%2,%3}, [%4];"
                 : "=r"(r0), "=r"(r1), "=r"(r2), "=r"(r3) : "r"(a));
}

// ---------------- prep 1: stable compaction of unmasked columns ----------------
__global__ __launch_bounds__(256)
void scan_kernel(const int* __restrict__ mask)
{
    __shared__ int cnt[256];
    const int b = blockIdx.x, tid = threadIdx.x;
    const int* mrow = mask + (size_t)b * SEQ;
    int mv[8], loc[8], c = 0;
    #pragma unroll
    for (int j = 0; j < 8; ++j) {
        mv[j] = mrow[tid * 8 + j];
        loc[j] = c;
        c += (mv[j] != 0);
    }
    cnt[tid] = c;
    __syncthreads();
    if (tid == 0) {
        int s = 0;
        for (int i = 0; i < 256; ++i) { int t = cnt[i]; cnt[i] = s; s += t; }
        g_nmask[b] = s;
    }
    __syncthreads();
    int base = cnt[tid];
    #pragma unroll
    for (int j = 0; j < 8; ++j)
        if (mv[j]) g_cmap[b * SEQ + base + loc[j]] = tid * 8 + j;
}

// ---------------- prep 2: gather K,V -> compacted fp16 ----------------
__global__ __launch_bounds__(256)
void gather_kernel(const float* __restrict__ K, const float* __restrict__ V)
{
    const int bh = blockIdx.y, b = bh >> 4;
    const int m0 = blockIdx.x * 128, tid = threadIdx.x;
    const int M = g_nmask[b];
    const float4* Kg = reinterpret_cast<const float4*>(K + (size_t)bh * SEQ * DK);
    const float4* Vg = reinterpret_cast<const float4*>(V + (size_t)bh * SEQ * DK);
    uint2* Kc = reinterpret_cast<uint2*>(g_Kc + (size_t)bh * SEQ * DK);
    uint2* Vc = reinterpret_cast<uint2*>(g_Vc + (size_t)bh * SEQ * DK);
    #pragma unroll
    for (int i = 0; i < 8; ++i) {
        int idx = i * 256 + tid;            // 128 keys x 16 chunks
        int ml = idx >> 4, c4 = idx & 15;
        int m = m0 + ml;
        uint2 ko = make_uint2(0, 0), vo = make_uint2(0, 0);
        if (m < M) {
            int col = g_cmap[b * SEQ + m];
            ko = f4h(Kg[(size_t)col * 16 + c4]);
            vo = f4h(Vg[(size_t)col * 16 + c4]);
        }
        Kc[(size_t)m * 16 + c4] = ko;
        Vc[(size_t)m * 16 + c4] = vo;
    }
}

// ---------------- main attention ----------------
__global__ __launch_bounds__(256, 2)
void attn_h16_kernel(const float* __restrict__ Q,
                     float* __restrict__ out,     // may be null
                     float* __restrict__ wout)    // may be null (normalized)
{
    __shared__ __align__(16) char smc[SMEM_BYTES];
    float* sadd  = reinterpret_cast<float*>(smc + ADDB);
    int*   scmap = reinterpret_cast<int*>(smc + CMB);
    float* sL    = reinterpret_cast<float*>(smc + LB);
    float* sIL   = reinterpret_cast<float*>(smc + ILB);

    const int tid  = threadIdx.x;
    const int lane = tid & 31;
    const int warp = tid >> 5;
    const int mw   = warp >> 1;          // 0..3 (16-q row tile)
    const int nw   = warp & 1;           // 0..1 (32-key half)
    const int g    = lane >> 2;          // 0..7
    const int tg   = lane & 3;           // 0..3

    const int bh = blockIdx.y;
    const int q0 = blockIdx.x * TQ;
    const int b  = bh >> 4;
    const int M  = g_nmask[b];
    const int NTb = (M + 63) >> 6;

    const uint32_t smb = (uint32_t)__cvta_generic_to_shared(smc);

    // ---- zero-prefill this CTA's 64x2048 weight block (fire-and-forget) ----
    if (wout) {
        float4 z = make_float4(0.f, 0.f, 0.f, 0.f);
        float4* wz = reinterpret_cast<float4*>(wout + ((size_t)bh * SEQ + q0) * SEQ);
        #pragma unroll 4
        for (int i = 0; i < 128; ++i)
            wz[i * 256 + tid] = z;
    }

    // ---- Q tile (scaled fp16), addends, column map ----
    {
        const float4* Qg = reinterpret_cast<const float4*>(
            Q + ((size_t)bh * SEQ + q0) * DK);
        #pragma unroll
        for (int i = 0; i < 4; ++i) {
            int fi = i * 256 + tid, row = fi >> 4, c4 = fi & 15;
            float4 v = Qg[fi];
            v.x *= 0.125f; v.y *= 0.125f; v.z *= 0.125f; v.w *= 0.125f;
            *reinterpret_cast<uint2*>(smc + QB + row * 144 + c4 * 8) = f4h(v);
        }
        #pragma unroll
        for (int i = 0; i < 8; ++i) {
            int k = i * 256 + tid;
            sadd[k]  = (k < M) ? -16.0f : -1e9f;
            scmap[k] = g_cmap[b * SEQ + k];
        }
    }
    __syncthreads();

    // ---- ldmatrix lane addressing ----
    const int laneRow = (lane & 7) + ((lane >> 3) & 1) * 8;
    const int laneSel = (lane >> 4) & 1;
    const uint32_t aBase = smb + QB + (uint32_t)(mw * 16 + laneRow) * 144 + laneSel * 16;
    const uint32_t bRowOff = (uint32_t)(nw * 32 + laneRow) * 144 + laneSel * 16;

    // ---- cache Q A-frags ----
    uint32_t qa[4][4];
    #pragma unroll
    for (int kc = 0; kc < 4; ++kc)
        ldsm4(qa[kc][0], qa[kc][1], qa[kc][2], qa[kc][3], aBase + kc * 32);

    const uint4* Kcg = reinterpret_cast<const uint4*>(g_Kc + (size_t)bh * SEQ * DK);
    const uint4* Vcg = reinterpret_cast<const uint4*>(g_Vc + (size_t)bh * SEQ * DK);

    // =============== PASS 1: L only (K double-buffered KB/VB) ===============
    float l0 = 0.f, l1 = 0.f;
    {
        uint4 kf[2];
        #pragma unroll
        for (int i = 0; i < 2; ++i) kf[i] = Kcg[i * 256 + tid];
        #pragma unroll
        for (int i = 0; i < 2; ++i) {
            int fi = i * 256 + tid;
            *reinterpret_cast<uint4*>(smc + KB + (fi >> 3) * 144 + (fi & 7) * 16) = kf[i];
        }
        __syncthreads();
        if (NTb > 1) {
            #pragma unroll
            for (int i = 0; i < 2; ++i) kf[i] = Kcg[512 + i * 256 + tid];
        }

        for (int t = 0; t < NTb; ++t) {
            const uint32_t curB = (t & 1) ? VB : KB;
            if (t + 1 < NTb) {
                const uint32_t nxtB = ((t + 1) & 1) ? VB : KB;
                #pragma unroll
                for (int i = 0; i < 2; ++i) {
                    int fi = i * 256 + tid;
                    *reinterpret_cast<uint4*>(smc + nxtB + (fi >> 3) * 144 + (fi & 7) * 16) = kf[i];
                }
            }
            if (t + 2 < NTb) {
                #pragma unroll
                for (int i = 0; i < 2; ++i)
                    kf[i] = Kcg[(size_t)(t + 2) * 512 + i * 256 + tid];
            }

            const uint32_t bB = smb + curB + bRowOff;
            float acc[4][4] = {};
            #pragma unroll
            for (int kc = 0; kc < 4; ++kc) {
                #pragma unroll
                for (int p = 0; p < 2; ++p) {
                    uint32_t r0, r1, r2, r3;
                    ldsm4(r0, r1, r2, r3, bB + p * (16 * 144) + kc * 32);
                    mma16(acc[2*p],   qa[kc][0], qa[kc][1], qa[kc][2], qa[kc][3], r0, r2);
                    mma16(acc[2*p+1], qa[kc][0], qa[kc][1], qa[kc][2], qa[kc][3], r1, r3);
                }
            }
            #pragma unroll
            for (int nt = 0; nt < 4; ++nt) {
                int colL = nw * 32 + nt * 8 + 2 * tg;
                float2 ad = *reinterpret_cast<const float2*>(sadd + t * TK + colL);
                l0 += __expf(acc[nt][0] + ad.x) + __expf(acc[nt][1] + ad.y);
                l1 += __expf(acc[nt][2] + ad.x) + __expf(acc[nt][3] + ad.y);
            }
            __syncthreads();
        }
    }

    // ---- reduce L; invL ----
    l0 += __shfl_xor_sync(~0u, l0, 1); l0 += __shfl_xor_sync(~0u, l0, 2);
    l1 += __shfl_xor_sync(~0u, l1, 1); l1 += __shfl_xor_sync(~0u, l1, 2);
    if (tg == 0) {
        sL[nw * TQ + mw * 16 + g]     = l0;
        sL[nw * TQ + mw * 16 + g + 8] = l1;
    }
    __syncthreads();
    if (tid < TQ)
        sIL[tid] = 1.0f / (sL[tid] + sL[TQ + tid]);
    __syncthreads();

    const float inv0 = sIL[mw * 16 + g];
    const float inv8 = sIL[mw * 16 + g + 8];

    // =============== PASS 2: QK recompute, scatter weights, PV ===============
    float o[8][4] = {};
    {
        uint4 kf[2];
        #pragma unroll
        for (int i = 0; i < 2; ++i) kf[i] = Kcg[i * 256 + tid];
        const uint32_t bBase = smb + KB + bRowOff;
        const uint32_t vBase = smb + VB + bRowOff;
        const size_t r0base = ((size_t)bh * SEQ + q0 + mw * 16 + g) * SEQ;

        for (int t = 0; t < NTb; ++t) {
            #pragma unroll
            for (int i = 0; i < 2; ++i) {
                int fi = i * 256 + tid;
                *reinterpret_cast<uint4*>(smc + KB + (fi >> 3) * 144 + (fi & 7) * 16) = kf[i];
            }
            __syncthreads();   // K(t) visible; PV(t-1) V reads done

            uint4 vf[2];
            #pragma unroll
            for (int i = 0; i < 2; ++i)
                vf[i] = Vcg[(size_t)t * 512 + i * 256 + tid];
            if (t + 1 < NTb) {
                #pragma unroll
                for (int i = 0; i < 2; ++i)
                    kf[i] = Kcg[(size_t)(t + 1) * 512 + i * 256 + tid];
            }

            float acc[4][4] = {};
            #pragma unroll
            for (int kc = 0; kc < 4; ++kc) {
                #pragma unroll
                for (int p = 0; p < 2; ++p) {
                    uint32_t r0, r1, r2, r3;
                    ldsm4(r0, r1, r2, r3, bBase + p * (16 * 144) + kc * 32);
                    mma16(acc[2*p],   qa[kc][0], qa[kc][1], qa[kc][2], qa[kc][3], r0, r2);
                    mma16(acc[2*p+1], qa[kc][0], qa[kc][1], qa[kc][2], qa[kc][3], r1, r3);
                }
            }

            // u = exp(s+ad); scatter normalized weights (guard u>0); fp16 P
            #pragma unroll
            for (int nt = 0; nt < 4; ++nt) {
                int colL = nw * 32 + nt * 8 + 2 * tg;
                int mcol = t * TK + colL;
                float2 ad = *reinterpret_cast<const float2*>(sadd + mcol);
                float u00 = __expf(acc[nt][0] + ad.x);
                float u01 = __expf(acc[nt][1] + ad.y);
                float u10 = __expf(acc[nt][2] + ad.x);
                float u11 = __expf(acc[nt][3] + ad.y);
                if (wout) {
                    int c0 = scmap[mcol], c1 = scmap[mcol + 1];
                    if (u00 > 0.f) wout[r0base + c0]           = u00 * inv0;
                    if (u01 > 0.f) wout[r0base + c1]           = u01 * inv0;
                    if (u10 > 0.f) wout[r0base + 8 * SEQ + c0] = u10 * inv8;
                    if (u11 > 0.f) wout[r0base + 8 * SEQ + c1] = u11 * inv8;
                }
                acc[nt][0] = u00; acc[nt][1] = u01;
                acc[nt][2] = u10; acc[nt][3] = u11;
            }
            uint32_t pa[2][4];
            #pragma unroll
            for (int kc = 0; kc < 2; ++kc) {
                pa[kc][0] = pack2(acc[2*kc][0]   * E16F, acc[2*kc][1]   * E16F);
                pa[kc][1] = pack2(acc[2*kc][2]   * E16F, acc[2*kc][3]   * E16F);
                pa[kc][2] = pack2(acc[2*kc+1][0] * E16F, acc[2*kc+1][1] * E16F);
                pa[kc][3] = pack2(acc[2*kc+1][2] * E16F, acc[2*kc+1][3] * E16F);
            }

            #pragma unroll
            for (int i = 0; i < 2; ++i) {
                int fi = i * 256 + tid;
                *reinterpret_cast<uint4*>(smc + VB + (fi >> 3) * 144 + (fi & 7) * 16) = vf[i];
            }
            __syncthreads();   // V(t) visible

            #pragma unroll
            for (int kc = 0; kc < 2; ++kc) {
                #pragma unroll
                for (int dp = 0; dp < 4; ++dp) {
                    uint32_t r0, r1, r2, r3;
                    ldsm4t(r0, r1, r2, r3, vBase + kc * (16 * 144) + dp * 32);
                    mma16(o[2*dp],   pa[kc][0], pa[kc][1], pa[kc][2], pa[kc][3], r0, r1);
                    mma16(o[2*dp+1], pa[kc][0], pa[kc][1], pa[kc][2], pa[kc][3], r2, r3);
                }
            }
        }
    }

    // ---- combine O across nw pair, normalize by inv*e^-16, write out ----
    __syncthreads();
    float* red = reinterpret_cast<float*>(smc);
    if (nw == 1) {
        #pragma unroll
        for (int dn = 0; dn < 8; ++dn) {
            int c = dn * 8 + 2 * tg;
            red[(mw * 16 + g) * 68 + c]         = o[dn][0];
            red[(mw * 16 + g) * 68 + c + 1]     = o[dn][1];
            red[(mw * 16 + g + 8) * 68 + c]     = o[dn][2];
            red[(mw * 16 + g + 8) * 68 + c + 1] = o[dn][3];
        }
    }
    __syncthreads();
    if (nw == 0 && out) {
        float s0 = inv0 * INVE16;
        float s8 = inv8 * INVE16;
        size_t base = ((size_t)bh * SEQ + q0 + mw * 16 + g) * DK;
        #pragma unroll
        for (int dn = 0; dn < 8; ++dn) {
            int c = dn * 8 + 2 * tg;
            float2 lo = make_float2((o[dn][0] + red[(mw * 16 + g) * 68 + c])     * s0,
                                    (o[dn][1] + red[(mw * 16 + g) * 68 + c + 1]) * s0);
            float2 hi = make_float2((o[dn][2] + red[(mw * 16 + g + 8) * 68 + c])     * s8,
                                    (o[dn][3] + red[(mw * 16 + g + 8) * 68 + c + 1]) * s8);
            *reinterpret_cast<float2*>(out + base + c)          = lo;
            *reinterpret_cast<float2*>(out + base + 8 * DK + c) = hi;
        }
    }
}

extern "C" void kernel_launch(void* const* d_in, const int* in_sizes, int n_in,
                              void* d_out, int out_size)
{
    const float* Q    = (const float*)d_in[0];
    const float* K    = (const float*)d_in[1];
    const float* V    = (const float*)d_in[2];
    const int*   mask = (const int*)d_in[3];

    const long long O = (long long)BH * SEQ * DK;    //   4,194,304
    const long long W = (long long)BH * SEQ * SEQ;   // 134,217,728

    float* out_ptr = nullptr;
    float* w_ptr   = nullptr;
    if ((long long)out_size >= O + W) {
        out_ptr = (float*)d_out;
        w_ptr   = (float*)d_out + O;
    } else if ((long long)out_size == W) {
        w_ptr   = (float*)d_out;
    } else {
        out_ptr = (float*)d_out;
    }

    scan_kernel<<<BATCH, 256>>>(mask);
    gather_kernel<<<dim3(SEQ / 128, BH), 256>>>(K, V);

    dim3 grid(SEQ / TQ, BH);
    attn_h16_kernel<<<grid, 256>>>(Q, out_ptr, w_ptr);
}

// round 14
// speedup vs baseline: 1.3005x; 1.3005x over previous
#include <cuda_runtime.h>
#include <cuda_fp16.h>
#include <cstdint>

// Fixed shapes
#define BATCH 2
#define HEADS 16
#define SEQ   2048
#define DK    64
#define BH    (BATCH*HEADS)

#define TQ 64            // query rows per CTA
#define TK 64            // keys per tile
#define NT (SEQ/TK)      // 32 tiles

// smem byte offsets (static buffer)
#define QB    0          // Q 64x64 half (9216)
#define KB    9216       // K buf0 / U tile (9216)
#define VB    18432      // K buf1 / V tile (9216)
#define ADDB  27648      // addend float[2048] (8192)
#define LB    35840      // L float[2][64] (512)
#define ILB   36352      // invL float[64] (256)
#define SMEM_BYTES 36608

#define E16F   8886110.5f      // e^16
#define INVE16 1.1253517e-7f   // e^-16

// static device scratch: fp16 K/V and the P=exp(s)*e^16 matrix
__device__ __half g_K16[(size_t)BH * SEQ * DK];     // 8 MB
__device__ __half g_V16[(size_t)BH * SEQ * DK];     // 8 MB
__device__ __half g_U[(size_t)BH * SEQ * SEQ];      // 268 MB

__device__ __forceinline__ uint32_t pack2(float lo, float hi) {
    __half2 h = __floats2half2_rn(lo, hi);
    return *reinterpret_cast<uint32_t*>(&h);
}
__device__ __forceinline__ uint2 f4h(float4 v) {
    return make_uint2(pack2(v.x, v.y), pack2(v.z, v.w));
}
__device__ __forceinline__ void mma16(float c[4],
                                      uint32_t a0, uint32_t a1, uint32_t a2, uint32_t a3,
                                      uint32_t b0, uint32_t b1) {
    asm volatile(
        "mma.sync.aligned.m16n8k16.row.col.f32.f16.f16.f32 "
        "{%0,%1,%2,%3}, {%4,%5,%6,%7}, {%8,%9}, {%0,%1,%2,%3};\n"
        : "+f"(c[0]), "+f"(c[1]), "+f"(c[2]), "+f"(c[3])
        : "r"(a0), "r"(a1), "r"(a2), "r"(a3), "r"(b0), "r"(b1));
}
__device__ __forceinline__ void ldsm4(uint32_t& r0, uint32_t& r1, uint32_t& r2, uint32_t& r3,
                                      uint32_t a) {
    asm volatile("ldmatrix.sync.aligned.m8n8.x4.shared.b16 {%0,%1,%2,%3}, [%4];"
                 : "=r"(r0), "=r"(r1), "=r"(r2), "=r"(r3) : "r"(a));
}
__device__ __forceinline__ void ldsm4t(uint32_t& r0, uint32_t& r1, uint32_t& r2, uint32_t& r3,
                                       uint32_t a) {
    asm volatile("ldmatrix.sync.aligned.m8n8.x4.trans.shared.b16 {%0,%1,%2,%3}, [%4];"
                 : "=r"(r0), "=r"(r1), "=r"(r2), "=r"(r3) : "r"(a));
}

// ---------------- prep: K,V -> fp16 ----------------
__global__ __launch_bounds__(256)
void cvt_kernel(const float* __restrict__ K, const float* __restrict__ V)
{
    size_t i = (size_t)blockIdx.x * 256 + threadIdx.x;   // over BH*SEQ*DK/4 = 1M float4
    reinterpret_cast<uint2*>(g_K16)[i] = f4h(reinterpret_cast<const float4*>(K)[i]);
    reinterpret_cast<uint2*>(g_V16)[i] = f4h(reinterpret_cast<const float4*>(V)[i]);
}

// ---------------- main attention ----------------
__global__ __launch_bounds__(256, 2)
void attn_h16_kernel(const float* __restrict__ Q,
                     const int*   __restrict__ mask,
                     float* __restrict__ out,     // may be null
                     float* __restrict__ wout)    // may be null (normalized)
{
    __shared__ __align__(16) char smc[SMEM_BYTES];
    float* sadd = reinterpret_cast<float*>(smc + ADDB);
    float* sL   = reinterpret_cast<float*>(smc + LB);
    float* sIL  = reinterpret_cast<float*>(smc + ILB);

    const int tid  = threadIdx.x;
    const int lane = tid & 31;
    const int warp = tid >> 5;
    const int mw   = warp >> 1;          // 0..3 (16-q row tile)
    const int nw   = warp & 1;           // 0..1 (32-key half)
    const int g    = lane >> 2;          // 0..7
    const int tg   = lane & 3;           // 0..3

    const int bh = blockIdx.y;
    const int q0 = blockIdx.x * TQ;
    const int b  = bh >> 4;

    const uint32_t smb = (uint32_t)__cvta_generic_to_shared(smc);

    // ---- Q tile (scaled fp16) + mask addend (-16 shift folded) ----
    {
        const float4* Qg = reinterpret_cast<const float4*>(
            Q + ((size_t)bh * SEQ + q0) * DK);
        #pragma unroll
        for (int i = 0; i < 4; ++i) {
            int fi = i * 256 + tid, row = fi >> 4, c4 = fi & 15;
            float4 v = Qg[fi];
            v.x *= 0.125f; v.y *= 0.125f; v.z *= 0.125f; v.w *= 0.125f;
            *reinterpret_cast<uint2*>(smc + QB + row * 144 + c4 * 8) = f4h(v);
        }
        const int* mrow = mask + (size_t)b * SEQ;
        #pragma unroll
        for (int i = 0; i < 8; ++i) {
            int k = i * 256 + tid;
            sadd[k] = mrow[k] ? -16.0f : -1e9f;
        }
    }
    __syncthreads();

    // ---- ldmatrix lane addressing ----
    const int laneRow = (lane & 7) + ((lane >> 3) & 1) * 8;
    const int laneSel = (lane >> 4) & 1;
    const uint32_t aBase   = smb + QB + (uint32_t)(mw * 16 + laneRow) * 144 + laneSel * 16;
    const uint32_t bRowOff = (uint32_t)(nw * 32 + laneRow) * 144 + laneSel * 16;

    // ---- cache Q A-frags ----
    uint32_t qa[4][4];
    #pragma unroll
    for (int kc = 0; kc < 4; ++kc)
        ldsm4(qa[kc][0], qa[kc][1], qa[kc][2], qa[kc][3], aBase + kc * 32);

    const uint4* K16g = reinterpret_cast<const uint4*>(g_K16 + (size_t)bh * SEQ * DK);
    const size_t wrow0 = ((size_t)bh * SEQ + q0 + mw * 16 + g) * SEQ;   // U/W row base (row g)

    // =============== PASS 1: QK + exp, store P=u*e^16 fp16, accumulate L ===============
    float l0 = 0.f, l1 = 0.f;
    {
        uint4 kf[2];
        #pragma unroll
        for (int i = 0; i < 2; ++i) kf[i] = K16g[i * 256 + tid];
        #pragma unroll
        for (int i = 0; i < 2; ++i) {
            int fi = i * 256 + tid;
            *reinterpret_cast<uint4*>(smc + KB + (fi >> 3) * 144 + (fi & 7) * 16) = kf[i];
        }
        __syncthreads();
        #pragma unroll
        for (int i = 0; i < 2; ++i) kf[i] = K16g[512 + i * 256 + tid];

        for (int t = 0; t < NT; ++t) {
            const uint32_t curB = (t & 1) ? VB : KB;
            if (t + 1 < NT) {
                const uint32_t nxtB = ((t + 1) & 1) ? VB : KB;
                #pragma unroll
                for (int i = 0; i < 2; ++i) {
                    int fi = i * 256 + tid;
                    *reinterpret_cast<uint4*>(smc + nxtB + (fi >> 3) * 144 + (fi & 7) * 16) = kf[i];
                }
            }
            if (t + 2 < NT) {
                #pragma unroll
                for (int i = 0; i < 2; ++i)
                    kf[i] = K16g[(size_t)(t + 2) * 512 + i * 256 + tid];
            }

            const uint32_t bB = smb + curB + bRowOff;
            float acc[4][4] = {};
            #pragma unroll
            for (int kc = 0; kc < 4; ++kc) {
                #pragma unroll
                for (int p = 0; p < 2; ++p) {
                    uint32_t r0, r1, r2, r3;
                    ldsm4(r0, r1, r2, r3, bB + p * (16 * 144) + kc * 32);
                    mma16(acc[2*p],   qa[kc][0], qa[kc][1], qa[kc][2], qa[kc][3], r0, r2);
                    mma16(acc[2*p+1], qa[kc][0], qa[kc][1], qa[kc][2], qa[kc][3], r1, r3);
                }
            }
            #pragma unroll
            for (int nt = 0; nt < 4; ++nt) {
                int colL = nw * 32 + nt * 8 + 2 * tg;
                float2 ad = *reinterpret_cast<const float2*>(sadd + t * TK + colL);
                float u00 = __expf(acc[nt][0] + ad.x);
                float u01 = __expf(acc[nt][1] + ad.y);
                float u10 = __expf(acc[nt][2] + ad.x);
                float u11 = __expf(acc[nt][3] + ad.y);
                l0 += u00 + u01;
                l1 += u10 + u11;
                size_t ub = wrow0 + t * TK + colL;
                *reinterpret_cast<uint32_t*>(g_U + ub)           = pack2(u00 * E16F, u01 * E16F);
                *reinterpret_cast<uint32_t*>(g_U + ub + 8 * SEQ) = pack2(u10 * E16F, u11 * E16F);
            }
            __syncthreads();
        }
    }

    // ---- reduce L; invL ----
    l0 += __shfl_xor_sync(~0u, l0, 1); l0 += __shfl_xor_sync(~0u, l0, 2);
    l1 += __shfl_xor_sync(~0u, l1, 1); l1 += __shfl_xor_sync(~0u, l1, 2);
    if (tg == 0) {
        sL[nw * TQ + mw * 16 + g]     = l0;
        sL[nw * TQ + mw * 16 + g + 8] = l1;
    }
    __syncthreads();
    if (tid < TQ)
        sIL[tid] = 1.0f / (sL[tid] + sL[TQ + tid]);
    __syncthreads();

    const float inv0 = sIL[mw * 16 + g];
    const float inv8 = sIL[mw * 16 + g + 8];

    // =============== PASS 2: stream U back, write W, PV (no K, no exp) ===============
    float o[8][4] = {};
    {
        const uint32_t uFragBase = smb + KB + (uint32_t)(mw * 16 + laneRow) * 144
                                 + nw * 64 + laneSel * 16;
        const uint32_t vBase = smb + VB + bRowOff;
        const __half* Ublk = g_U + (size_t)bh * SEQ * SEQ;
        const uint4* V16g = reinterpret_cast<const uint4*>(g_V16 + (size_t)bh * SEQ * DK);
        const float sW0 = inv0 * INVE16;
        const float sW8 = inv8 * INVE16;

        uint4 uf[2], vf[2];
        #pragma unroll
        for (int i = 0; i < 2; ++i) {
            int fi = i * 256 + tid, row = fi >> 3, c = fi & 7;
            uf[i] = reinterpret_cast<const uint4*>(Ublk + (size_t)(q0 + row) * SEQ)[c];
            vf[i] = V16g[fi];
        }

        for (int t = 0; t < NT; ++t) {
            // STS U(t) -> KB  (KB readers of t-1 finished before sync2(t-1))
            #pragma unroll
            for (int i = 0; i < 2; ++i) {
                int fi = i * 256 + tid;
                *reinterpret_cast<uint4*>(smc + KB + (fi >> 3) * 144 + (fi & 7) * 16) = uf[i];
            }
            __syncthreads();   // sync1: U(t) visible; PV(t-1) V reads done

            // STS V(t) -> VB
            #pragma unroll
            for (int i = 0; i < 2; ++i) {
                int fi = i * 256 + tid;
                *reinterpret_cast<uint4*>(smc + VB + (fi >> 3) * 144 + (fi & 7) * 16) = vf[i];
            }
            // prefetch t+1
            if (t + 1 < NT) {
                #pragma unroll
                for (int i = 0; i < 2; ++i) {
                    int fi = i * 256 + tid, row = fi >> 3, c = fi & 7;
                    uf[i] = reinterpret_cast<const uint4*>(
                        Ublk + (size_t)(q0 + row) * SEQ + (t + 1) * 64)[c];
                    vf[i] = V16g[(size_t)(t + 1) * 512 + fi];
                }
            }

            // ldsm P A-frags from U tile; write W from frags
            uint32_t pa[2][4];
            #pragma unroll
            for (int kc = 0; kc < 2; ++kc)
                ldsm4(pa[kc][0], pa[kc][1], pa[kc][2], pa[kc][3], uFragBase + kc * 32);
            if (wout) {
                size_t rbase = wrow0 + t * TK;
                #pragma unroll
                for (int kc = 0; kc < 2; ++kc) {
                    int c = nw * 32 + kc * 16 + 2 * tg;
                    float2 x;
                    x = __half22float2(*reinterpret_cast<__half2*>(&pa[kc][0]));
                    *reinterpret_cast<float2*>(wout + rbase + c) = make_float2(x.x * sW0, x.y * sW0);
                    x = __half22float2(*reinterpret_cast<__half2*>(&pa[kc][1]));
                    *reinterpret_cast<float2*>(wout + rbase + 8 * SEQ + c) = make_float2(x.x * sW8, x.y * sW8);
                    x = __half22float2(*reinterpret_cast<__half2*>(&pa[kc][2]));
                    *reinterpret_cast<float2*>(wout + rbase + c + 8) = make_float2(x.x * sW0, x.y * sW0);
                    x = __half22float2(*reinterpret_cast<__half2*>(&pa[kc][3]));
                    *reinterpret_cast<float2*>(wout + rbase + 8 * SEQ + c + 8) = make_float2(x.x * sW8, x.y * sW8);
                }
            }
            __syncthreads();   // sync2: V(t) visible; U ldsm done

            // PV
            #pragma unroll
            for (int kc = 0; kc < 2; ++kc) {
                #pragma unroll
                for (int dp = 0; dp < 4; ++dp) {
                    uint32_t r0, r1, r2, r3;
                    ldsm4t(r0, r1, r2, r3, vBase + kc * (16 * 144) + dp * 32);
                    mma16(o[2*dp],   pa[kc][0], pa[kc][1], pa[kc][2], pa[kc][3], r0, r1);
                    mma16(o[2*dp+1], pa[kc][0], pa[kc][1], pa[kc][2], pa[kc][3], r2, r3);
                }
            }
        }
    }

    // ---- combine O across nw pair, normalize by inv*e^-16, write out ----
    __syncthreads();
    float* red = reinterpret_cast<float*>(smc);
    if (nw == 1) {
        #pragma unroll
        for (int dn = 0; dn < 8; ++dn) {
            int c = dn * 8 + 2 * tg;
            red[(mw * 16 + g) * 68 + c]         = o[dn][0];
            red[(mw * 16 + g) * 68 + c + 1]     = o[dn][1];
            red[(mw * 16 + g + 8) * 68 + c]     = o[dn][2];
            red[(mw * 16 + g + 8) * 68 + c + 1] = o[dn][3];
        }
    }
    __syncthreads();
    if (nw == 0 && out) {
        float s0 = inv0 * INVE16;
        float s8 = inv8 * INVE16;
        size_t base = ((size_t)bh * SEQ + q0 + mw * 16 + g) * DK;
        #pragma unroll
        for (int dn = 0; dn < 8; ++dn) {
            int c = dn * 8 + 2 * tg;
            float2 lo = make_float2((o[dn][0] + red[(mw * 16 + g) * 68 + c])     * s0,
                                    (o[dn][1] + red[(mw * 16 + g) * 68 + c + 1]) * s0);
            float2 hi = make_float2((o[dn][2] + red[(mw * 16 + g + 8) * 68 + c])     * s8,
                                    (o[dn][3] + red[(mw * 16 + g + 8) * 68 + c + 1]) * s8);
            *reinterpret_cast<float2*>(out + base + c)          = lo;
            *reinterpret_cast<float2*>(out + base + 8 * DK + c) = hi;
        }
    }
}

extern "C" void kernel_launch(void* const* d_in, const int* in_sizes, int n_in,
                              void* d_out, int out_size)
{
    const float* Q    = (const float*)d_in[0];
    const float* K    = (const float*)d_in[1];
    const float* V    = (const float*)d_in[2];
    const int*   mask = (const int*)d_in[3];

    const long long O = (long long)BH * SEQ * DK;    //   4,194,304
    const long long W = (long long)BH * SEQ * SEQ;   // 134,217,728

    float* out_ptr = nullptr;
    float* w_ptr   = nullptr;
    if ((long long)out_size >= O + W) {
        out_ptr = (float*)d_out;
        w_ptr   = (float*)d_out + O;
    } else if ((long long)out_size == W) {
        w_ptr   = (float*)d_out;
    } else {
        out_ptr = (float*)d_out;
    }

    // K,V -> fp16 (BH*SEQ*DK/4 float4 = 1,048,576 -> 4096 blocks)
    cvt_kernel<<<4096, 256>>>(K, V);

    dim3 grid(SEQ / TQ, BH);
    attn_h16_kernel<<<grid, 256>>>(Q, mask, out_ptr, w_ptr);
}

// round 15
// speedup vs baseline: 1.4606x; 1.1231x over previous
#include <cuda_runtime.h>
#include <cuda_fp16.h>
#include <cstdint>

// Fixed shapes
#define BATCH 2
#define HEADS 16
#define SEQ   2048
#define DK    64
#define BH    (BATCH*HEADS)

#define TQ 64            // query rows per CTA
#define TK 64            // keys per tile
#define NT (SEQ/TK)      // 32 tiles

// smem byte offsets (static buffer)
#define QB    0          // Q 64x64 half (9216)
#define KB    9216       // K buf0 / pass2 K tile (9216)
#define VB    18432      // K buf1 / pass2 V tile (9216)
#define ADDB  27648      // addend float[2048] (8192)
#define LB    35840      // L partials float[4][64] (1024)
#define ILB   36864      // invL float[64] (256)
#define SMEM_BYTES 37120

#define E16F   8886110.5f      // e^16
#define INVE16 1.1253517e-7f   // e^-16

// fp16 K/V scratch (16 MB static)
__device__ __half g_K16[(size_t)BH * SEQ * DK];
__device__ __half g_V16[(size_t)BH * SEQ * DK];

__device__ __forceinline__ uint32_t pack2(float lo, float hi) {
    __half2 h = __floats2half2_rn(lo, hi);
    return *reinterpret_cast<uint32_t*>(&h);
}
__device__ __forceinline__ uint2 f4h(float4 v) {
    return make_uint2(pack2(v.x, v.y), pack2(v.z, v.w));
}
__device__ __forceinline__ void mma16(float c[4],
                                      uint32_t a0, uint32_t a1, uint32_t a2, uint32_t a3,
                                      uint32_t b0, uint32_t b1) {
    asm volatile(
        "mma.sync.aligned.m16n8k16.row.col.f32.f16.f16.f32 "
        "{%0,%1,%2,%3}, {%4,%5,%6,%7}, {%8,%9}, {%0,%1,%2,%3};\n"
        : "+f"(c[0]), "+f"(c[1]), "+f"(c[2]), "+f"(c[3])
        : "r"(a0), "r"(a1), "r"(a2), "r"(a3), "r"(b0), "r"(b1));
}
__device__ __forceinline__ void ldsm4(uint32_t& r0, uint32_t& r1, uint32_t& r2, uint32_t& r3,
                                      uint32_t a) {
    asm volatile("ldmatrix.sync.aligned.m8n8.x4.shared.b16 {%0,%1,%2,%3}, [%4];"
                 : "=r"(r0), "=r"(r1), "=r"(r2), "=r"(r3) : "r"(a));
}
__device__ __forceinline__ void ldsm4t(uint32_t& r0, uint32_t& r1, uint32_t& r2, uint32_t& r3,
                                       uint32_t a) {
    asm volatile("ldmatrix.sync.aligned.m8n8.x4.trans.shared.b16 {%0,%1,%2,%3}, [%4];"
                 : "=r"(r0), "=r"(r1), "=r"(r2), "=r"(r3) : "r"(a));
}

// ---------------- prep: K,V -> fp16 ----------------
__global__ __launch_bounds__(256)
void cvt_kernel(const float* __restrict__ K, const float* __restrict__ V)
{
    size_t i = (size_t)blockIdx.x * 256 + threadIdx.x;   // BH*SEQ*DK/4 = 1M float4
    reinterpret_cast<uint2*>(g_K16)[i] = f4h(reinterpret_cast<const float4*>(K)[i]);
    reinterpret_cast<uint2*>(g_V16)[i] = f4h(reinterpret_cast<const float4*>(V)[i]);
}

// ---------------- main attention ----------------
__global__ __launch_bounds__(256, 2)
void attn_h16_kernel(const float* __restrict__ Q,
                     const int*   __restrict__ mask,
                     float* __restrict__ out,     // may be null
                     float* __restrict__ wout)    // may be null (normalized)
{
    __shared__ __align__(16) char smc[SMEM_BYTES];
    float* sadd = reinterpret_cast<float*>(smc + ADDB);
    float* sL   = reinterpret_cast<float*>(smc + LB);
    float* sIL  = reinterpret_cast<float*>(smc + ILB);

    const int tid  = threadIdx.x;
    const int lane = tid & 31;
    const int warp = tid >> 5;
    const int g    = lane >> 2;          // 0..7
    const int tg   = lane & 3;           // 0..3

    const int bh = blockIdx.y;
    const int q0 = blockIdx.x * TQ;
    const int b  = bh >> 4;

    const uint32_t smb = (uint32_t)__cvta_generic_to_shared(smc);

    // ---- Q tile (scaled fp16) + mask addend (-16 shift folded) ----
    {
        const float4* Qg = reinterpret_cast<const float4*>(
            Q + ((size_t)bh * SEQ + q0) * DK);
        #pragma unroll
        for (int i = 0; i < 4; ++i) {
            int fi = i * 256 + tid, row = fi >> 4, c4 = fi & 15;
            float4 v = Qg[fi];
            v.x *= 0.125f; v.y *= 0.125f; v.z *= 0.125f; v.w *= 0.125f;
            *reinterpret_cast<uint2*>(smc + QB + row * 144 + c4 * 8) = f4h(v);
        }
        const int* mrow = mask + (size_t)b * SEQ;
        #pragma unroll
        for (int i = 0; i < 8; ++i) {
            int k = i * 256 + tid;
            sadd[k] = mrow[k] ? -16.0f : -1e9f;
        }
    }
    __syncthreads();

    // ---- ldmatrix lane addressing ----
    const int laneRow = (lane & 7) + ((lane >> 3) & 1) * 8;
    const int laneSel = (lane >> 4) & 1;

    const uint4* K16g = reinterpret_cast<const uint4*>(g_K16 + (size_t)bh * SEQ * DK);
    const uint4* V16g = reinterpret_cast<const uint4*>(g_V16 + (size_t)bh * SEQ * DK);

    // =============== PASS 1: L only. Warp = m32 x n16 (Wm=2, Wn=4) ===============
    {
        const int mw2 = warp >> 2;       // 0..1  (m32 block)
        const int nw4 = warp & 3;        // 0..3  (n16 block)
        const uint32_t b1 = smb + (uint32_t)((nw4 * 16 + laneRow) * 144 + laneSel * 16);

        // A frags for 2 m-tiles (B-frags reused across both -> halved ldsm)
        uint32_t qa1[2][4][4];
        #pragma unroll
        for (int i = 0; i < 2; ++i) {
            uint32_t a = smb + QB + (uint32_t)((mw2 * 32 + i * 16 + laneRow) * 144 + laneSel * 16);
            #pragma unroll
            for (int kc = 0; kc < 4; ++kc)
                ldsm4(qa1[i][kc][0], qa1[i][kc][1], qa1[i][kc][2], qa1[i][kc][3], a + kc * 32);
        }

        float lg[2][2] = {};   // [m-tile][row-half g / g+8]

        uint4 kf[2];
        #pragma unroll
        for (int i = 0; i < 2; ++i) kf[i] = K16g[i * 256 + tid];
        #pragma unroll
        for (int i = 0; i < 2; ++i) {
            int fi = i * 256 + tid;
            *reinterpret_cast<uint4*>(smc + KB + (fi >> 3) * 144 + (fi & 7) * 16) = kf[i];
        }
        __syncthreads();
        #pragma unroll
        for (int i = 0; i < 2; ++i) kf[i] = K16g[512 + i * 256 + tid];

        for (int t = 0; t < NT; ++t) {
            const uint32_t curB = (t & 1) ? VB : KB;
            if (t + 1 < NT) {
                const uint32_t nxtB = ((t + 1) & 1) ? VB : KB;
                #pragma unroll
                for (int i = 0; i < 2; ++i) {
                    int fi = i * 256 + tid;
                    *reinterpret_cast<uint4*>(smc + nxtB + (fi >> 3) * 144 + (fi & 7) * 16) = kf[i];
                }
            }
            if (t + 2 < NT) {
                #pragma unroll
                for (int i = 0; i < 2; ++i)
                    kf[i] = K16g[(size_t)(t + 2) * 512 + i * 256 + tid];
            }

            // QK: 4 ldsm.x4, 16 mma (B-frags shared across 2 m-tiles)
            float acc[2][2][4] = {};
            #pragma unroll
            for (int kc = 0; kc < 4; ++kc) {
                uint32_t r0, r1, r2, r3;
                ldsm4(r0, r1, r2, r3, curB + b1 - smb + smb + kc * 32);   // curB + b1row
                // (address: smb + curB + rowoff + kc*32)
                #pragma unroll
                for (int i = 0; i < 2; ++i) {
                    mma16(acc[i][0], qa1[i][kc][0], qa1[i][kc][1], qa1[i][kc][2], qa1[i][kc][3], r0, r2);
                    mma16(acc[i][1], qa1[i][kc][0], qa1[i][kc][1], qa1[i][kc][2], qa1[i][kc][3], r1, r3);
                }
            }

            // exp + L (same arithmetic order as pass 2 -> bitwise-identical S)
            #pragma unroll
            for (int i = 0; i < 2; ++i) {
                #pragma unroll
                for (int p = 0; p < 2; ++p) {
                    int colL = nw4 * 16 + p * 8 + 2 * tg;
                    float2 ad = *reinterpret_cast<const float2*>(sadd + t * TK + colL);
                    lg[i][0] += __expf(acc[i][p][0] + ad.x) + __expf(acc[i][p][1] + ad.y);
                    lg[i][1] += __expf(acc[i][p][2] + ad.x) + __expf(acc[i][p][3] + ad.y);
                }
            }
            __syncthreads();
        }

        // quad reduce, stash partials by nw4
        #pragma unroll
        for (int i = 0; i < 2; ++i) {
            #pragma unroll
            for (int h = 0; h < 2; ++h) {
                lg[i][h] += __shfl_xor_sync(~0u, lg[i][h], 1);
                lg[i][h] += __shfl_xor_sync(~0u, lg[i][h], 2);
            }
        }
        if (tg == 0) {
            #pragma unroll
            for (int i = 0; i < 2; ++i) {
                sL[nw4 * TQ + mw2 * 32 + i * 16 + g]     = lg[i][0];
                sL[nw4 * TQ + mw2 * 32 + i * 16 + g + 8] = lg[i][1];
            }
        }
        __syncthreads();
        if (tid < TQ)
            sIL[tid] = 1.0f / (sL[tid] + sL[TQ + tid] + sL[2 * TQ + tid] + sL[3 * TQ + tid]);
        __syncthreads();
    }

    // =============== PASS 2: QK recompute, normalized W, PV (round-12 layout) ===============
    const int mw = warp >> 1;            // 0..3
    const int nw = warp & 1;             // 0..1
    const uint32_t aBase   = smb + QB + (uint32_t)((mw * 16 + laneRow) * 144 + laneSel * 16);
    const uint32_t bRowOff = (uint32_t)((nw * 32 + laneRow) * 144 + laneSel * 16);

    uint32_t qa[4][4];
    #pragma unroll
    for (int kc = 0; kc < 4; ++kc)
        ldsm4(qa[kc][0], qa[kc][1], qa[kc][2], qa[kc][3], aBase + kc * 32);

    const float inv0 = sIL[mw * 16 + g];
    const float inv8 = sIL[mw * 16 + g + 8];

    float o[8][4] = {};
    {
        uint4 kf[2];
        #pragma unroll
        for (int i = 0; i < 2; ++i) kf[i] = K16g[i * 256 + tid];
        const uint32_t bBase = smb + KB + bRowOff;
        const uint32_t vBase = smb + VB + bRowOff;

        for (int t = 0; t < NT; ++t) {
            #pragma unroll
            for (int i = 0; i < 2; ++i) {
                int fi = i * 256 + tid;
                *reinterpret_cast<uint4*>(smc + KB + (fi >> 3) * 144 + (fi & 7) * 16) = kf[i];
            }
            __syncthreads();   // K(t) visible; PV(t-1) V reads done

            uint4 vf[2];
            #pragma unroll
            for (int i = 0; i < 2; ++i)
                vf[i] = V16g[(size_t)t * 512 + i * 256 + tid];
            if (t + 1 < NT) {
                #pragma unroll
                for (int i = 0; i < 2; ++i)
                    kf[i] = K16g[(size_t)(t + 1) * 512 + i * 256 + tid];
            }

            float acc[4][4] = {};
            #pragma unroll
            for (int kc = 0; kc < 4; ++kc) {
                #pragma unroll
                for (int p = 0; p < 2; ++p) {
                    uint32_t r0, r1, r2, r3;
                    ldsm4(r0, r1, r2, r3, bBase + p * (16 * 144) + kc * 32);
                    mma16(acc[2*p],   qa[kc][0], qa[kc][1], qa[kc][2], qa[kc][3], r0, r2);
                    mma16(acc[2*p+1], qa[kc][0], qa[kc][1], qa[kc][2], qa[kc][3], r1, r3);
                }
            }

            // u = exp(s+ad); write NORMALIZED weights; fp16 P = u*e^16
            #pragma unroll
            for (int nt = 0; nt < 4; ++nt) {
                int colL = nw * 32 + nt * 8 + 2 * tg;
                float2 ad = *reinterpret_cast<const float2*>(sadd + t * TK + colL);
                float u00 = __expf(acc[nt][0] + ad.x);
                float u01 = __expf(acc[nt][1] + ad.y);
                float u10 = __expf(acc[nt][2] + ad.x);
                float u11 = __expf(acc[nt][3] + ad.y);
                if (wout) {
                    size_t base = ((size_t)bh * SEQ + q0 + mw * 16 + g) * SEQ + t * TK + colL;
                    *reinterpret_cast<float2*>(wout + base)           = make_float2(u00 * inv0, u01 * inv0);
                    *reinterpret_cast<float2*>(wout + base + 8 * SEQ) = make_float2(u10 * inv8, u11 * inv8);
                }
                acc[nt][0] = u00; acc[nt][1] = u01;
                acc[nt][2] = u10; acc[nt][3] = u11;
            }
            uint32_t pa[2][4];
            #pragma unroll
            for (int kc = 0; kc < 2; ++kc) {
                pa[kc][0] = pack2(acc[2*kc][0]   * E16F, acc[2*kc][1]   * E16F);
                pa[kc][1] = pack2(acc[2*kc][2]   * E16F, acc[2*kc][3]   * E16F);
                pa[kc][2] = pack2(acc[2*kc+1][0] * E16F, acc[2*kc+1][1] * E16F);
                pa[kc][3] = pack2(acc[2*kc+1][2] * E16F, acc[2*kc+1][3] * E16F);
            }

            #pragma unroll
            for (int i = 0; i < 2; ++i) {
                int fi = i * 256 + tid;
                *reinterpret_cast<uint4*>(smc + VB + (fi >> 3) * 144 + (fi & 7) * 16) = vf[i];
            }
            __syncthreads();   // V(t) visible

            #pragma unroll
            for (int kc = 0; kc < 2; ++kc) {
                #pragma unroll
                for (int dp = 0; dp < 4; ++dp) {
                    uint32_t r0, r1, r2, r3;
                    ldsm4t(r0, r1, r2, r3, vBase + kc * (16 * 144) + dp * 32);
                    mma16(o[2*dp],   pa[kc][0], pa[kc][1], pa[kc][2], pa[kc][3], r0, r1);
                    mma16(o[2*dp+1], pa[kc][0], pa[kc][1], pa[kc][2], pa[kc][3], r2, r3);
                }
            }
        }
    }

    // ---- combine O across nw pair, normalize by inv*e^-16, write out ----
    __syncthreads();
    float* red = reinterpret_cast<float*>(smc);
    if (nw == 1) {
        #pragma unroll
        for (int dn = 0; dn < 8; ++dn) {
            int c = dn * 8 + 2 * tg;
            red[(mw * 16 + g) * 68 + c]         = o[dn][0];
            red[(mw * 16 + g) * 68 + c + 1]     = o[dn][1];
            red[(mw * 16 + g + 8) * 68 + c]     = o[dn][2];
            red[(mw * 16 + g + 8) * 68 + c + 1] = o[dn][3];
        }
    }
    __syncthreads();
    if (nw == 0 && out) {
        float s0 = inv0 * INVE16;
        float s8 = inv8 * INVE16;
        size_t base = ((size_t)bh * SEQ + q0 + mw * 16 + g) * DK;
        #pragma unroll
        for (int dn = 0; dn < 8; ++dn) {
            int c = dn * 8 + 2 * tg;
            float2 lo = make_float2((o[dn][0] + red[(mw * 16 + g) * 68 + c])     * s0,
                                    (o[dn][1] + red[(mw * 16 + g) * 68 + c + 1]) * s0);
            float2 hi = make_float2((o[dn][2] + red[(mw * 16 + g + 8) * 68 + c])     * s8,
                                    (o[dn][3] + red[(mw * 16 + g + 8) * 68 + c + 1]) * s8);
            *reinterpret_cast<float2*>(out + base + c)          = lo;
            *reinterpret_cast<float2*>(out + base + 8 * DK + c) = hi;
        }
    }
}

extern "C" void kernel_launch(void* const* d_in, const int* in_sizes, int n_in,
                              void* d_out, int out_size)
{
    const float* Q    = (const float*)d_in[0];
    const float* K    = (const float*)d_in[1];
    const float* V    = (const float*)d_in[2];
    const int*   mask = (const int*)d_in[3];

    const long long O = (long long)BH * SEQ * DK;    //   4,194,304
    const long long W = (long long)BH * SEQ * SEQ;   // 134,217,728

    float* out_ptr = nullptr;
    float* w_ptr   = nullptr;
    if ((long long)out_size >= O + W) {
        out_ptr = (float*)d_out;
        w_ptr   = (float*)d_out + O;
    } else if ((long long)out_size == W) {
        w_ptr   = (float*)d_out;
    } else {
        out_ptr = (float*)d_out;
    }

    cvt_kernel<<<4096, 256>>>(K, V);

    dim3 grid(SEQ / TQ, BH);
    attn_h16_kernel<<<grid, 256>>>(Q, mask, out_ptr, w_ptr);
}